// round 16
// baseline (speedup 1.0000x reference)
#include <cuda_runtime.h>
#include <cuda_bf16.h>
#include <cstdint>

#define NN 50000
#define EE 800000
#define EPN (EE + NN)
#define HC 256
#define NH 4
#define NSCB 196

// ----------------------------- scratch ---------------------------------------
__device__ int g_is64;
__device__ int g_src[EE];
__device__ int g_dst[EE];
__device__ int g_cnt[NN];
__device__ int g_loc[NN];
__device__ int g_bsum[256];
__device__ int g_bpre[256];
__device__ int g_segoff[NN + 1];
__device__ int g_fill[NN];
__device__ int g_ssrc[EPN];
__device__ __align__(16) float    g_h[NN * HC];
__device__ __align__(16) float    g_agg[NN * HC];
__device__ __align__(16) float    g_act[NN * 64];
__device__ __align__(16) __nv_bfloat16 g_WTh[3 * 256 * 256];
__device__ __align__(16) __nv_bfloat16 g_WTl[3 * 256 * 256];
__device__ __align__(16) float    g_s[NN * NH];
__device__ __align__(16) float    g_dv[NN * NH];
__device__ float g_cs[HC], g_css[HC], g_scale[HC], g_shift[HC];

// ----------------------------- helpers ---------------------------------------
__device__ __forceinline__ float lrelu(float x, float s) { return x > 0.f ? x : s * x; }
__device__ __forceinline__ void red_add(float* p, float v) {
    asm volatile("red.global.add.f32 [%0], %1;" :: "l"(p), "f"(v) : "memory");
}
__device__ __forceinline__ uint32_t s2u(const void* p) {
    uint32_t a;
    asm("{ .reg .u64 t; cvta.to.shared.u64 t, %1; cvt.u32.u64 %0, t; }" : "=r"(a) : "l"(p));
    return a;
}
__device__ __forceinline__ void ldsm4(uint32_t* r, uint32_t addr) {
    asm volatile("ldmatrix.sync.aligned.m8n8.x4.shared.b16 {%0,%1,%2,%3}, [%4];"
                 : "=r"(r[0]), "=r"(r[1]), "=r"(r[2]), "=r"(r[3]) : "r"(addr));
}
__device__ __forceinline__ void mma16816(float* d, const uint32_t* a, const uint32_t* b) {
    asm volatile("mma.sync.aligned.m16n8k16.row.col.f32.bf16.bf16.f32 "
                 "{%0,%1,%2,%3},{%4,%5,%6,%7},{%8,%9},{%0,%1,%2,%3};"
                 : "+f"(d[0]), "+f"(d[1]), "+f"(d[2]), "+f"(d[3])
                 : "r"(a[0]), "r"(a[1]), "r"(a[2]), "r"(a[3]), "r"(b[0]), "r"(b[1]));
}
__device__ __forceinline__ uint32_t pack_hi(float a, float b, float& ra, float& rb) {
    __nv_bfloat16 ha = __float2bfloat16(a), hb = __float2bfloat16(b);
    ra = a - __bfloat162float(ha);
    rb = b - __bfloat162float(hb);
    return ((uint32_t)__bfloat16_as_ushort(hb) << 16) | (uint32_t)__bfloat16_as_ushort(ha);
}
__device__ __forceinline__ uint32_t pack_lo(float ra, float rb) {
    __nv_bfloat16 la = __float2bfloat16(ra), lb = __float2bfloat16(rb);
    return ((uint32_t)__bfloat16_as_ushort(lb) << 16) | (uint32_t)__bfloat16_as_ushort(la);
}

// ----------------------------- zcnt (+detect) / convert+hist -----------------
__global__ void k_zcnt(const void* p) {
    int i = blockIdx.x * blockDim.x + threadIdx.x;
    if (i < NN) g_cnt[i] = 1;          // self loop pre-counted
    if (i == 0) {
        const long long* q = (const long long*)p;
        int ok = 1;
        for (int j = 0; j < 8; j++) {
            long long v = q[j];
            if (v < 0 || v >= NN) ok = 0;
        }
        g_is64 = ok;
    }
}
__global__ void k_convhist(const void* p) {
    int i = blockIdx.x * blockDim.x + threadIdx.x;
    if (i >= 2 * EE) return;
    long long v = g_is64 ? ((const long long*)p)[i] : (long long)(((const int*)p)[i]);
    int x = (int)v;
    if (i < EE) {
        g_src[i] = x;
    } else {
        g_dst[i - EE] = x;
        atomicAdd(&g_cnt[x], 1);
    }
}

// ----------------------------- scan + scatter ---------------------------------
__global__ void k_scan1(void) {
    __shared__ int sh[256];
    int t = threadIdx.x, b = blockIdx.x;
    int i = b * 256 + t;
    int v = (i < NN) ? g_cnt[i] : 0;
    sh[t] = v;
    __syncthreads();
#pragma unroll
    for (int off = 1; off < 256; off <<= 1) {
        int add = (t >= off) ? sh[t - off] : 0;
        __syncthreads();
        sh[t] += add;
        __syncthreads();
    }
    if (i < NN) g_loc[i] = sh[t] - v;
    if (t == 255) g_bsum[b] = sh[t];
}
__global__ void k_scan2(void) {
    __shared__ int sh[256];
    int t = threadIdx.x;
    int v = (t < NSCB) ? g_bsum[t] : 0;
    sh[t] = v;
    __syncthreads();
#pragma unroll
    for (int off = 1; off < 256; off <<= 1) {
        int add = (t >= off) ? sh[t - off] : 0;
        __syncthreads();
        sh[t] += add;
        __syncthreads();
    }
    g_bpre[t] = sh[t] - v;
}
__global__ void k_scan3(void) {
    int i = blockIdx.x * blockDim.x + threadIdx.x;
    if (i >= NN) return;
    int off = g_loc[i] + g_bpre[i >> 8];
    g_segoff[i] = off;
    g_fill[i] = off;
    if (i == 0) g_segoff[NN] = EPN;
}
__global__ void k_scatter(void) {
    int t = blockIdx.x * blockDim.x + threadIdx.x;
    if (t >= EPN) return;
    int s, d;
    if (t < EE) { s = g_src[t]; d = g_dst[t]; } else { s = t - EE; d = s; }
    int pos = atomicAdd(&g_fill[d], 1);
    g_ssrc[pos] = s;
}

// ----------------------------- weight split -----------------------------------
__global__ void k_prep_w(const float* __restrict__ W, int L) {
    int n = blockIdx.x, k = threadIdx.x;
    float w = W[k * 256 + n];
    size_t o = (size_t)L * 65536 + n * 256 + k;
    __nv_bfloat16 h = __float2bfloat16(w);
    g_WTh[o] = h;
    g_WTl[o] = __float2bfloat16(w - __bfloat162float(h));
}

// ----------------------------- mma.sync GEMM (CTA 128x128) + fused s/d -------
// 8 warps = 4M x 2N ; warp tile 32M x 64N (one head per warp's columns).
#define KCH 32
#define ROWB 80
#define OA_H 0
#define OA_L (OA_H + 128 * ROWB)     // 10240
#define OB_H (OA_L + 128 * ROWB)     // 20480
#define OB_L (OB_H + 128 * ROWB)     // 30720
#define SMEM_SZ (OB_L + 128 * ROWB)  // 40960

template <bool AFF>
__global__ __launch_bounds__(256) void k_gemm(
    const float* __restrict__ Asrc,
    const __nv_bfloat16* __restrict__ Bh, const __nv_bfloat16* __restrict__ Bl,
    const float* __restrict__ as_, const float* __restrict__ ad_,
    float* __restrict__ C) {
    __shared__ __align__(16) char smem[SMEM_SZ];
    const uint32_t sb = s2u(smem);
    const int tid = threadIdx.x;
    const int wid = tid >> 5, lane = tid & 31;
    const int m0 = blockIdx.x * 128;
    const int n0 = blockIdx.y * 128;
    const int wm = (wid >> 1) * 32;
    const int wn = (wid & 1) * 64;

    float acc[2][8][4];
#pragma unroll
    for (int i = 0; i < 2; i++)
#pragma unroll
        for (int j = 0; j < 8; j++)
#pragma unroll
            for (int q = 0; q < 4; q++) acc[i][j][q] = 0.f;

    const int lq = lane >> 3, lr = lane & 7;

    for (int ch = 0; ch < 8; ch++) {
        const int k0 = ch * KCH;
        __syncthreads();
        // A: 128 rows x 32 cols, fp32 -> on-the-fly affine + hi/lo split
#pragma unroll
        for (int s = tid; s < 512; s += 256) {
            int r = s >> 2, kq = s & 3;
            int gr = m0 + r;
            int c0 = k0 + kq * 8;
            float v[8];
            if (gr < NN) {
                const float4* ap = (const float4*)(Asrc + (size_t)gr * HC + c0);
                float4 f0 = ap[0], f1 = ap[1];
                v[0] = f0.x; v[1] = f0.y; v[2] = f0.z; v[3] = f0.w;
                v[4] = f1.x; v[5] = f1.y; v[6] = f1.z; v[7] = f1.w;
                if (AFF) {
#pragma unroll
                    for (int j = 0; j < 8; j++)
                        v[j] = lrelu(fmaf(v[j], g_scale[c0 + j], g_shift[c0 + j]), 0.01f);
                }
            } else {
#pragma unroll
                for (int j = 0; j < 8; j++) v[j] = 0.f;
            }
            uint32_t ph[4], pl[4];
#pragma unroll
            for (int j = 0; j < 4; j++) {
                float ra, rb;
                ph[j] = pack_hi(v[2 * j], v[2 * j + 1], ra, rb);
                pl[j] = pack_lo(ra, rb);
            }
            *(uint4*)(smem + OA_H + r * ROWB + kq * 16) = make_uint4(ph[0], ph[1], ph[2], ph[3]);
            *(uint4*)(smem + OA_L + r * ROWB + kq * 16) = make_uint4(pl[0], pl[1], pl[2], pl[3]);
        }
        // B: 128 n-rows x 32 k-cols
#pragma unroll
        for (int s = tid; s < 512; s += 256) {
            int r = s >> 2, kq = s & 3;
            uint4 vh = *(const uint4*)(Bh + (size_t)(n0 + r) * HC + k0 + kq * 8);
            uint4 vl = *(const uint4*)(Bl + (size_t)(n0 + r) * HC + k0 + kq * 8);
            *(uint4*)(smem + OB_H + r * ROWB + kq * 16) = vh;
            *(uint4*)(smem + OB_L + r * ROWB + kq * 16) = vl;
        }
        __syncthreads();

#pragma unroll
        for (int ks = 0; ks < 2; ks++) {
            uint32_t ah[2][4], al[2][4], bh[4][4], bl[4][4];
#pragma unroll
            for (int mt = 0; mt < 2; mt++) {
                int row = wm + mt * 16 + (lq & 1) * 8 + lr;
                int u = ks * 2 + (lq >> 1);
                ldsm4(ah[mt], sb + OA_H + row * ROWB + u * 16);
                ldsm4(al[mt], sb + OA_L + row * ROWB + u * 16);
            }
#pragma unroll
            for (int p = 0; p < 4; p++) {
                int n = wn + p * 16 + (lq >> 1) * 8 + lr;
                int u = ks * 2 + (lq & 1);
                ldsm4(bh[p], sb + OB_H + n * ROWB + u * 16);
                ldsm4(bl[p], sb + OB_L + n * ROWB + u * 16);
            }
#pragma unroll
            for (int mt = 0; mt < 2; mt++)
#pragma unroll
                for (int nt = 0; nt < 8; nt++) {
                    const uint32_t* ph = &bh[nt >> 1][(nt & 1) * 2];
                    const uint32_t* pl = &bl[nt >> 1][(nt & 1) * 2];
                    mma16816(acc[mt][nt], ah[mt], ph);
                    mma16816(acc[mt][nt], ah[mt], pl);
                    mma16816(acc[mt][nt], al[mt], ph);
                }
        }
    }

    const int g = lane >> 2, tg = lane & 3;
    // C store
#pragma unroll
    for (int mt = 0; mt < 2; mt++) {
        int r0 = m0 + wm + mt * 16 + g;
#pragma unroll
        for (int nt = 0; nt < 8; nt++) {
            int c = n0 + wn + nt * 8 + tg * 2;
            if (r0 < NN)
                *(float2*)(C + (size_t)r0 * HC + c) = make_float2(acc[mt][nt][0], acc[mt][nt][1]);
            if (r0 + 8 < NN)
                *(float2*)(C + (size_t)(r0 + 8) * HC + c) = make_float2(acc[mt][nt][2], acc[mt][nt][3]);
        }
    }

    // fused per-head logits: warp's 64 columns == one head
    const int head = blockIdx.y * 2 + (wid & 1);
    float s_part[4] = {0.f, 0.f, 0.f, 0.f}, d_part[4] = {0.f, 0.f, 0.f, 0.f};
#pragma unroll
    for (int mt = 0; mt < 2; mt++)
#pragma unroll
        for (int nt = 0; nt < 8; nt++) {
            int c = nt * 8 + tg * 2;            // head-local column
            float a0 = __ldg(as_ + head * 64 + c), a1 = __ldg(as_ + head * 64 + c + 1);
            float e0 = __ldg(ad_ + head * 64 + c), e1 = __ldg(ad_ + head * 64 + c + 1);
            s_part[mt * 2 + 0] += acc[mt][nt][0] * a0 + acc[mt][nt][1] * a1;
            s_part[mt * 2 + 1] += acc[mt][nt][2] * a0 + acc[mt][nt][3] * a1;
            d_part[mt * 2 + 0] += acc[mt][nt][0] * e0 + acc[mt][nt][1] * e1;
            d_part[mt * 2 + 1] += acc[mt][nt][2] * e0 + acc[mt][nt][3] * e1;
        }
#pragma unroll
    for (int off = 1; off < 4; off <<= 1)
#pragma unroll
        for (int r = 0; r < 4; r++) {
            s_part[r] += __shfl_xor_sync(0xffffffffu, s_part[r], off);
            d_part[r] += __shfl_xor_sync(0xffffffffu, d_part[r], off);
        }
    if (tg == 0) {
#pragma unroll
        for (int r = 0; r < 4; r++) {
            int row = m0 + wm + (r >> 1) * 16 + g + (r & 1) * 8;
            if (row < NN) {
                g_s[row * NH + head]  = s_part[r];
                g_dv[row * NH + head] = d_part[r];
            }
        }
    }
}

// ----------------------------- fused GAT (single pass, pipelined) + stats ----
__global__ __launch_bounds__(256) void k_gat(const float* __restrict__ bias, int mode) {
    __shared__ float sv[8][256];
    int n = (blockIdx.x * blockDim.x + threadIdx.x) >> 5;
    int lane = threadIdx.x & 31;
    int wz = threadIdx.x >> 5;
    int p0 = __ldg(&g_segoff[n]);
    int p1 = __ldg(&g_segoff[n + 1]);
    float4 d4 = *(const float4*)(g_dv + n * NH);

    const bool hi = (lane >= 16);
    float4 den = make_float4(0.f, 0.f, 0.f, 0.f);
    float4 accA = make_float4(0.f, 0.f, 0.f, 0.f);
    float4 accB = make_float4(0.f, 0.f, 0.f, 0.f);

    // pipeline: data for edge p staged one iter ahead; index two ahead
    int sCur = __ldg(&g_ssrc[p0]);
    float4 svN = *(const float4*)(g_s + sCur * NH);
    const float4* hpN = (const float4*)(g_h + (size_t)sCur * HC);
    float4 v0N = __ldg(hpN + lane);
    float4 v1N = __ldg(hpN + lane + 32);
    int sNext = (p0 + 1 < p1) ? __ldg(&g_ssrc[p0 + 1]) : 0;

    for (int p = p0; p < p1; p++) {
        float4 sval = svN;
        float4 v0 = v0N, v1 = v1N;
        int sp = sNext;
        if (p + 1 < p1) {
            svN = *(const float4*)(g_s + sp * NH);
            const float4* hp2 = (const float4*)(g_h + (size_t)sp * HC);
            v0N = __ldg(hp2 + lane);
            v1N = __ldg(hp2 + lane + 32);
        }
        if (p + 2 < p1) sNext = __ldg(&g_ssrc[p + 2]);

        float e0 = __expf(lrelu(sval.x + d4.x, 0.2f));
        float e1 = __expf(lrelu(sval.y + d4.y, 0.2f));
        float e2 = __expf(lrelu(sval.z + d4.z, 0.2f));
        float e3 = __expf(lrelu(sval.w + d4.w, 0.2f));
        den.x += e0; den.y += e1; den.z += e2; den.w += e3;
        float w0 = hi ? e1 : e0;
        float w1 = hi ? e3 : e2;
        accA.x = fmaf(w0, v0.x, accA.x); accA.y = fmaf(w0, v0.y, accA.y);
        accA.z = fmaf(w0, v0.z, accA.z); accA.w = fmaf(w0, v0.w, accA.w);
        accB.x = fmaf(w1, v1.x, accB.x); accB.y = fmaf(w1, v1.y, accB.y);
        accB.z = fmaf(w1, v1.z, accB.z); accB.w = fmaf(w1, v1.w, accB.w);
    }
    float inv0 = 1.f / (hi ? den.y : den.x);
    float inv1 = 1.f / (hi ? den.w : den.z);
    accA.x *= inv0; accA.y *= inv0; accA.z *= inv0; accA.w *= inv0;
    accB.x *= inv1; accB.y *= inv1; accB.z *= inv1; accB.w *= inv1;

    if (mode == 0) {
        float4* op = (float4*)(g_agg + (size_t)n * HC);
        op[lane] = accA;
        op[lane + 32] = accB;
        float4 bA = __ldg(((const float4*)bias) + lane);
        float4 bB = __ldg(((const float4*)bias) + lane + 32);
        *(float4*)&sv[wz][lane * 4] = make_float4(accA.x + bA.x, accA.y + bA.y,
                                                  accA.z + bA.z, accA.w + bA.w);
        *(float4*)&sv[wz][(lane + 32) * 4] = make_float4(accB.x + bB.x, accB.y + bB.y,
                                                         accB.z + bB.z, accB.w + bB.w);
        __syncthreads();
        int c = threadIdx.x;
        float s = 0.f, ss = 0.f;
#pragma unroll
        for (int w = 0; w < 8; w++) {
            float xv = sv[w][c];
            s += xv; ss += xv * xv;
        }
        red_add(&g_cs[c], s);
        red_add(&g_css[c], ss);
    } else {
        float4 tA, tB;
        tA.x = __shfl_xor_sync(0xffffffffu, accA.x, 16);
        tA.y = __shfl_xor_sync(0xffffffffu, accA.y, 16);
        tA.z = __shfl_xor_sync(0xffffffffu, accA.z, 16);
        tA.w = __shfl_xor_sync(0xffffffffu, accA.w, 16);
        tB.x = __shfl_xor_sync(0xffffffffu, accB.x, 16);
        tB.y = __shfl_xor_sync(0xffffffffu, accB.y, 16);
        tB.z = __shfl_xor_sync(0xffffffffu, accB.z, 16);
        tB.w = __shfl_xor_sync(0xffffffffu, accB.w, 16);
        if (!hi) {
            float4 m = make_float4(0.25f * (accA.x + tA.x + accB.x + tB.x),
                                   0.25f * (accA.y + tA.y + accB.y + tB.y),
                                   0.25f * (accA.z + tA.z + accB.z + tB.z),
                                   0.25f * (accA.w + tA.w + accB.w + tB.w));
            *(float4*)(g_act + (size_t)n * 64 + lane * 4) = m;
            float4 b4 = __ldg(((const float4*)bias) + lane);
            *(float4*)&sv[wz][lane * 4] = make_float4(m.x + b4.x, m.y + b4.y,
                                                      m.z + b4.z, m.w + b4.w);
        }
        __syncthreads();
        int c = threadIdx.x;
        if (c < 64) {
            float s = 0.f, ss = 0.f;
#pragma unroll
            for (int w = 0; w < 8; w++) {
                float xv = sv[w][c];
                s += xv; ss += xv * xv;
            }
            red_add(&g_cs[c], s);
            red_add(&g_css[c], ss);
        }
    }
}

// ----------------------------- scale (folds bias; self-zeroes stats) ---------
__global__ void k_scale(const float* __restrict__ ga, const float* __restrict__ gw,
                        const float* __restrict__ gb, const float* __restrict__ bias) {
    int c = threadIdx.x;
    float inv_n = 1.0f / (float)NN;
    float mu = g_cs[c] * inv_n;
    float ex2 = g_css[c] * inv_n;
    float a = ga[c];
    float var = ex2 - 2.f * a * mu * mu + a * a * mu * mu;
    float inv = rsqrtf(var + 1e-5f);
    float sc = gw[c] * inv;
    g_scale[c] = sc;
    g_shift[c] = gb[c] - sc * a * mu + sc * bias[c];
    g_cs[c] = 0.f;
    g_css[c] = 0.f;
}

// ----------------------------- fused norm + 3-layer MLP ----------------------
__global__ __launch_bounds__(256) void k_mlp(
    const float* __restrict__ mW0, const float* __restrict__ mb0,
    const float* __restrict__ mW1, const float* __restrict__ mb1,
    const float* __restrict__ mW2, const float* __restrict__ mb2,
    float* __restrict__ out) {
    __shared__ float W0s[64 * 32], W1s[32 * 16], W2s[16 * 2];
    __shared__ float b0s[32], b1s[16], b2s[2];
    int tid = threadIdx.x;
    for (int i = tid; i < 64 * 32; i += 256) W0s[i] = mW0[i];
    for (int i = tid; i < 32 * 16; i += 256) W1s[i] = mW1[i];
    if (tid < 32) W2s[tid] = mW2[tid];
    if (tid < 32) b0s[tid] = mb0[tid];
    if (tid < 16) b1s[tid] = mb1[tid];
    if (tid < 2)  b2s[tid] = mb2[tid];
    __syncthreads();

    int node = blockIdx.x * 256 + tid;
    if (node >= NN) return;

    float h1[32];
#pragma unroll
    for (int j = 0; j < 32; j++) h1[j] = b0s[j];
    const float* xr = g_act + (size_t)node * 64;
#pragma unroll 4
    for (int k = 0; k < 64; k++) {
        float v = lrelu(fmaf(xr[k], g_scale[k], g_shift[k]), 0.01f);
        const float4* wr = (const float4*)(W0s + k * 32);
#pragma unroll
        for (int j = 0; j < 8; j++) {
            float4 w = wr[j];
            h1[4 * j + 0] = fmaf(v, w.x, h1[4 * j + 0]);
            h1[4 * j + 1] = fmaf(v, w.y, h1[4 * j + 1]);
            h1[4 * j + 2] = fmaf(v, w.z, h1[4 * j + 2]);
            h1[4 * j + 3] = fmaf(v, w.w, h1[4 * j + 3]);
        }
    }
    float h2[16];
#pragma unroll
    for (int j = 0; j < 16; j++) h2[j] = b1s[j];
#pragma unroll
    for (int k = 0; k < 32; k++) {
        float v = fmaxf(h1[k], 0.f);
        const float4* wr = (const float4*)(W1s + k * 16);
#pragma unroll
        for (int j = 0; j < 4; j++) {
            float4 w = wr[j];
            h2[4 * j + 0] = fmaf(v, w.x, h2[4 * j + 0]);
            h2[4 * j + 1] = fmaf(v, w.y, h2[4 * j + 1]);
            h2[4 * j + 2] = fmaf(v, w.z, h2[4 * j + 2]);
            h2[4 * j + 3] = fmaf(v, w.w, h2[4 * j + 3]);
        }
    }
    float o0 = b2s[0], o1 = b2s[1];
#pragma unroll
    for (int k = 0; k < 16; k++) {
        float v = fmaxf(h2[k], 0.f);
        o0 = fmaf(v, W2s[k * 2], o0);
        o1 = fmaf(v, W2s[k * 2 + 1], o1);
    }
    *(float2*)(out + (size_t)node * 2) = make_float2(o0, o1);
}

// ----------------------------- driver ----------------------------------------
extern "C" void kernel_launch(void* const* d_in, const int* in_sizes, int n_in,
                              void* d_out, int out_size) {
    const float* x  = (const float*)d_in[0];
    const void*  ei = d_in[1];
    const float* W[3]   = { (const float*)d_in[2],  (const float*)d_in[9],  (const float*)d_in[16] };
    const float* as_[3] = { (const float*)d_in[3],  (const float*)d_in[10], (const float*)d_in[17] };
    const float* ad_[3] = { (const float*)d_in[4],  (const float*)d_in[11], (const float*)d_in[18] };
    const float* b_[3]  = { (const float*)d_in[5],  (const float*)d_in[12], (const float*)d_in[19] };
    const float* gw_[3] = { (const float*)d_in[6],  (const float*)d_in[13], (const float*)d_in[20] };
    const float* gb_[3] = { (const float*)d_in[7],  (const float*)d_in[14], (const float*)d_in[21] };
    const float* ga_[3] = { (const float*)d_in[8],  (const float*)d_in[15], (const float*)d_in[22] };
    const float* mW0 = (const float*)d_in[23]; const float* mb0 = (const float*)d_in[24];
    const float* mW1 = (const float*)d_in[25]; const float* mb1 = (const float*)d_in[26];
    const float* mW2 = (const float*)d_in[27]; const float* mb2 = (const float*)d_in[28];
    float* out = (float*)d_out;

    float* d_h;   cudaGetSymbolAddress((void**)&d_h,   g_h);
    float* d_agg; cudaGetSymbolAddress((void**)&d_agg, g_agg);
    __nv_bfloat16* d_WTh; cudaGetSymbolAddress((void**)&d_WTh, g_WTh);
    __nv_bfloat16* d_WTl; cudaGetSymbolAddress((void**)&d_WTl, g_WTl);

    // second stream for the edge-sort preamble (event fork/join; capturable)
    static cudaStream_t s2 = nullptr;
    static cudaEvent_t ev_fork = nullptr, ev_join = nullptr;
    if (!s2) {
        cudaStreamCreateWithFlags(&s2, cudaStreamNonBlocking);
        cudaEventCreateWithFlags(&ev_fork, cudaEventDisableTiming);
        cudaEventCreateWithFlags(&ev_join, cudaEventDisableTiming);
    }

    cudaEventRecord(ev_fork, 0);
    cudaStreamWaitEvent(s2, ev_fork, 0);
    k_zcnt<<<(NN + 255) / 256, 256, 0, s2>>>(ei);
    k_convhist<<<(2 * EE + 255) / 256, 256, 0, s2>>>(ei);
    k_scan1<<<NSCB, 256, 0, s2>>>();
    k_scan2<<<1, 256, 0, s2>>>();
    k_scan3<<<(NN + 255) / 256, 256, 0, s2>>>();
    k_scatter<<<(EPN + 255) / 256, 256, 0, s2>>>();
    cudaEventRecord(ev_join, s2);

    // main stream: weights + layer-0 GEMM overlap with the sort
    for (int L = 0; L < 3; L++) k_prep_w<<<256, 256>>>(W[L], L);

    const int GB = (NN + 127) / 128;
    for (int L = 0; L < 3; L++) {
        const float* Asrc = (L == 0) ? x : d_agg;
        if (L == 0)
            k_gemm<false><<<dim3(GB, 2), 256>>>(Asrc, d_WTh + (size_t)L * 65536,
                                                d_WTl + (size_t)L * 65536, as_[L], ad_[L], d_h);
        else
            k_gemm<true><<<dim3(GB, 2), 256>>>(Asrc, d_WTh + (size_t)L * 65536,
                                               d_WTl + (size_t)L * 65536, as_[L], ad_[L], d_h);
        if (L == 0) cudaStreamWaitEvent(0, ev_join, 0);   // sort must be done before gat
        int mode = (L == 2) ? 1 : 0;
        k_gat<<<(NN * 32 + 255) / 256, 256>>>(b_[L], mode);
        k_scale<<<1, (L == 2) ? 64 : 256>>>(ga_[L], gw_[L], gb_[L], b_[L]);
    }

    k_mlp<<<(NN + 255) / 256, 256>>>(mW0, mb0, mW1, mb1, mW2, mb2, out);
}

// round 17
// speedup vs baseline: 1.1792x; 1.1792x over previous
#include <cuda_runtime.h>
#include <cuda_bf16.h>
#include <cstdint>

#define NN 50000
#define EE 800000
#define EPN (EE + NN)
#define HC 256
#define NH 4
#define NSCB 196

// ----------------------------- scratch ---------------------------------------
__device__ int g_is64;
__device__ int g_src[EE];
__device__ int g_dst[EE];
__device__ int g_cnt[NN];
__device__ int g_loc[NN];
__device__ int g_bsum[256];
__device__ int g_bpre[256];
__device__ int g_segoff[NN + 1];
__device__ int g_fill[NN];
__device__ int g_ssrc[EPN];
__device__ __align__(16) float    g_h[NN * HC];
__device__ __align__(16) float    g_agg[NN * HC];
__device__ __align__(16) float    g_act[NN * 64];
__device__ __align__(16) __nv_bfloat16 g_WTh[3 * 256 * 256];
__device__ __align__(16) __nv_bfloat16 g_WTl[3 * 256 * 256];
__device__ __align__(16) float    g_s[NN * NH];
__device__ __align__(16) float    g_dv[NN * NH];
__device__ float g_cs[HC], g_css[HC], g_scale[HC], g_shift[HC];

// ----------------------------- helpers ---------------------------------------
__device__ __forceinline__ float lrelu(float x, float s) { return x > 0.f ? x : s * x; }
__device__ __forceinline__ void red_add(float* p, float v) {
    asm volatile("red.global.add.f32 [%0], %1;" :: "l"(p), "f"(v) : "memory");
}
__device__ __forceinline__ uint32_t s2u(const void* p) {
    uint32_t a;
    asm("{ .reg .u64 t; cvta.to.shared.u64 t, %1; cvt.u32.u64 %0, t; }" : "=r"(a) : "l"(p));
    return a;
}
__device__ __forceinline__ void ldsm4(uint32_t* r, uint32_t addr) {
    asm volatile("ldmatrix.sync.aligned.m8n8.x4.shared.b16 {%0,%1,%2,%3}, [%4];"
                 : "=r"(r[0]), "=r"(r[1]), "=r"(r[2]), "=r"(r[3]) : "r"(addr));
}
__device__ __forceinline__ void mma16816(float* d, const uint32_t* a, const uint32_t* b) {
    asm volatile("mma.sync.aligned.m16n8k16.row.col.f32.bf16.bf16.f32 "
                 "{%0,%1,%2,%3},{%4,%5,%6,%7},{%8,%9},{%0,%1,%2,%3};"
                 : "+f"(d[0]), "+f"(d[1]), "+f"(d[2]), "+f"(d[3])
                 : "r"(a[0]), "r"(a[1]), "r"(a[2]), "r"(a[3]), "r"(b[0]), "r"(b[1]));
}
__device__ __forceinline__ uint32_t pack_hi(float a, float b, float& ra, float& rb) {
    __nv_bfloat16 ha = __float2bfloat16(a), hb = __float2bfloat16(b);
    ra = a - __bfloat162float(ha);
    rb = b - __bfloat162float(hb);
    return ((uint32_t)__bfloat16_as_ushort(hb) << 16) | (uint32_t)__bfloat16_as_ushort(ha);
}
__device__ __forceinline__ uint32_t pack_lo(float ra, float rb) {
    __nv_bfloat16 la = __float2bfloat16(ra), lb = __float2bfloat16(rb);
    return ((uint32_t)__bfloat16_as_ushort(lb) << 16) | (uint32_t)__bfloat16_as_ushort(la);
}

// ----------------------------- zcnt (+detect) / convert+hist -----------------
__global__ void k_zcnt(const void* p) {
    int i = blockIdx.x * blockDim.x + threadIdx.x;
    if (i < NN) g_cnt[i] = 1;          // self loop pre-counted
    if (i == 0) {
        const long long* q = (const long long*)p;
        int ok = 1;
        for (int j = 0; j < 8; j++) {
            long long v = q[j];
            if (v < 0 || v >= NN) ok = 0;
        }
        g_is64 = ok;
    }
}
__global__ void k_convhist(const void* p) {
    int i = blockIdx.x * blockDim.x + threadIdx.x;
    if (i >= 2 * EE) return;
    long long v = g_is64 ? ((const long long*)p)[i] : (long long)(((const int*)p)[i]);
    int x = (int)v;
    if (i < EE) {
        g_src[i] = x;
    } else {
        g_dst[i - EE] = x;
        atomicAdd(&g_cnt[x], 1);
    }
}

// ----------------------------- scan + scatter ---------------------------------
__global__ void k_scan1(void) {
    __shared__ int sh[256];
    int t = threadIdx.x, b = blockIdx.x;
    int i = b * 256 + t;
    int v = (i < NN) ? g_cnt[i] : 0;
    sh[t] = v;
    __syncthreads();
#pragma unroll
    for (int off = 1; off < 256; off <<= 1) {
        int add = (t >= off) ? sh[t - off] : 0;
        __syncthreads();
        sh[t] += add;
        __syncthreads();
    }
    if (i < NN) g_loc[i] = sh[t] - v;
    if (t == 255) g_bsum[b] = sh[t];
}
__global__ void k_scan2(void) {
    __shared__ int sh[256];
    int t = threadIdx.x;
    int v = (t < NSCB) ? g_bsum[t] : 0;
    sh[t] = v;
    __syncthreads();
#pragma unroll
    for (int off = 1; off < 256; off <<= 1) {
        int add = (t >= off) ? sh[t - off] : 0;
        __syncthreads();
        sh[t] += add;
        __syncthreads();
    }
    g_bpre[t] = sh[t] - v;
}
__global__ void k_scan3(void) {
    int i = blockIdx.x * blockDim.x + threadIdx.x;
    if (i >= NN) return;
    int off = g_loc[i] + g_bpre[i >> 8];
    g_segoff[i] = off;
    g_fill[i] = off;
    if (i == 0) g_segoff[NN] = EPN;
}
__global__ void k_scatter(void) {
    int t = blockIdx.x * blockDim.x + threadIdx.x;
    if (t >= EPN) return;
    int s, d;
    if (t < EE) { s = g_src[t]; d = g_dst[t]; } else { s = t - EE; d = s; }
    int pos = atomicAdd(&g_fill[d], 1);
    g_ssrc[pos] = s;
}

// ----------------------------- weight split -----------------------------------
__global__ void k_prep_w(const float* __restrict__ W, int L) {
    int n = blockIdx.x, k = threadIdx.x;
    float w = W[k * 256 + n];
    size_t o = (size_t)L * 65536 + n * 256 + k;
    __nv_bfloat16 h = __float2bfloat16(w);
    g_WTh[o] = h;
    g_WTl[o] = __float2bfloat16(w - __bfloat162float(h));
}

// ----------------------------- mma.sync GEMM + fused s/d ---------------------
#define KCH 32
#define ROWB 80
#define OA_H 0
#define OA_L (OA_H + 128 * ROWB)
#define OB_H (OA_L + 128 * ROWB)
#define OB_L (OB_H + 64 * ROWB)
#define SMEM_SZ (OB_L + 64 * ROWB)

template <bool AFF>
__global__ __launch_bounds__(256) void k_gemm(
    const float* __restrict__ Asrc,
    const __nv_bfloat16* __restrict__ Bh, const __nv_bfloat16* __restrict__ Bl,
    const float* __restrict__ as_, const float* __restrict__ ad_,
    float* __restrict__ C) {
    __shared__ __align__(16) char smem[SMEM_SZ];
    const uint32_t sb = s2u(smem);
    const int tid = threadIdx.x;
    const int wid = tid >> 5, lane = tid & 31;
    const int m0 = blockIdx.x * 128;
    const int n0 = blockIdx.y * 64;
    const int wm = (wid >> 1) * 32;
    const int wn = (wid & 1) * 32;

    float acc[2][4][4];
#pragma unroll
    for (int i = 0; i < 2; i++)
#pragma unroll
        for (int j = 0; j < 4; j++)
#pragma unroll
            for (int q = 0; q < 4; q++) acc[i][j][q] = 0.f;

    const int lq = lane >> 3, lr = lane & 7;

    for (int ch = 0; ch < 8; ch++) {
        const int k0 = ch * KCH;
        __syncthreads();
#pragma unroll
        for (int s = tid; s < 512; s += 256) {
            int r = s >> 2, kq = s & 3;
            int gr = m0 + r;
            int c0 = k0 + kq * 8;
            float v[8];
            if (gr < NN) {
                const float4* ap = (const float4*)(Asrc + (size_t)gr * HC + c0);
                float4 f0 = ap[0], f1 = ap[1];
                v[0] = f0.x; v[1] = f0.y; v[2] = f0.z; v[3] = f0.w;
                v[4] = f1.x; v[5] = f1.y; v[6] = f1.z; v[7] = f1.w;
                if (AFF) {
#pragma unroll
                    for (int j = 0; j < 8; j++)
                        v[j] = lrelu(fmaf(v[j], g_scale[c0 + j], g_shift[c0 + j]), 0.01f);
                }
            } else {
#pragma unroll
                for (int j = 0; j < 8; j++) v[j] = 0.f;
            }
            uint32_t ph[4], pl[4];
#pragma unroll
            for (int j = 0; j < 4; j++) {
                float ra, rb;
                ph[j] = pack_hi(v[2 * j], v[2 * j + 1], ra, rb);
                pl[j] = pack_lo(ra, rb);
            }
            *(uint4*)(smem + OA_H + r * ROWB + kq * 16) = make_uint4(ph[0], ph[1], ph[2], ph[3]);
            *(uint4*)(smem + OA_L + r * ROWB + kq * 16) = make_uint4(pl[0], pl[1], pl[2], pl[3]);
        }
        {
            int r = tid >> 2, kq = tid & 3;
            uint4 vh = *(const uint4*)(Bh + (size_t)(n0 + r) * HC + k0 + kq * 8);
            uint4 vl = *(const uint4*)(Bl + (size_t)(n0 + r) * HC + k0 + kq * 8);
            *(uint4*)(smem + OB_H + r * ROWB + kq * 16) = vh;
            *(uint4*)(smem + OB_L + r * ROWB + kq * 16) = vl;
        }
        __syncthreads();

#pragma unroll
        for (int ks = 0; ks < 2; ks++) {
            uint32_t ah[2][4], al[2][4], bh[2][4], bl[2][4];
#pragma unroll
            for (int mt = 0; mt < 2; mt++) {
                int row = wm + mt * 16 + (lq & 1) * 8 + lr;
                int u = ks * 2 + (lq >> 1);
                ldsm4(ah[mt], sb + OA_H + row * ROWB + u * 16);
                ldsm4(al[mt], sb + OA_L + row * ROWB + u * 16);
            }
#pragma unroll
            for (int p = 0; p < 2; p++) {
                int n = wn + p * 16 + (lq >> 1) * 8 + lr;
                int u = ks * 2 + (lq & 1);
                ldsm4(bh[p], sb + OB_H + n * ROWB + u * 16);
                ldsm4(bl[p], sb + OB_L + n * ROWB + u * 16);
            }
#pragma unroll
            for (int mt = 0; mt < 2; mt++)
#pragma unroll
                for (int nt = 0; nt < 4; nt++) {
                    const uint32_t* ph = &bh[nt >> 1][(nt & 1) * 2];
                    const uint32_t* pl = &bl[nt >> 1][(nt & 1) * 2];
                    mma16816(acc[mt][nt], ah[mt], ph);
                    mma16816(acc[mt][nt], ah[mt], pl);
                    mma16816(acc[mt][nt], al[mt], ph);
                }
        }
    }

    const int g = lane >> 2, tg = lane & 3;
    // C store
#pragma unroll
    for (int mt = 0; mt < 2; mt++) {
        int r0 = m0 + wm + mt * 16 + g;
#pragma unroll
        for (int nt = 0; nt < 4; nt++) {
            int c = n0 + wn + nt * 8 + tg * 2;
            if (r0 < NN)
                *(float2*)(C + (size_t)r0 * HC + c) = make_float2(acc[mt][nt][0], acc[mt][nt][1]);
            if (r0 + 8 < NN)
                *(float2*)(C + (size_t)(r0 + 8) * HC + c) = make_float2(acc[mt][nt][2], acc[mt][nt][3]);
        }
    }

    // fused per-head logits (head == blockIdx.y); cross-half combine in smem
    const int head = blockIdx.y;
    float s_part[4] = {0.f, 0.f, 0.f, 0.f}, d_part[4] = {0.f, 0.f, 0.f, 0.f};
#pragma unroll
    for (int mt = 0; mt < 2; mt++)
#pragma unroll
        for (int nt = 0; nt < 4; nt++) {
            int c = wn + nt * 8 + tg * 2;
            float a0 = __ldg(as_ + head * 64 + c), a1 = __ldg(as_ + head * 64 + c + 1);
            float e0 = __ldg(ad_ + head * 64 + c), e1 = __ldg(ad_ + head * 64 + c + 1);
            s_part[mt * 2 + 0] += acc[mt][nt][0] * a0 + acc[mt][nt][1] * a1;
            s_part[mt * 2 + 1] += acc[mt][nt][2] * a0 + acc[mt][nt][3] * a1;
            d_part[mt * 2 + 0] += acc[mt][nt][0] * e0 + acc[mt][nt][1] * e1;
            d_part[mt * 2 + 1] += acc[mt][nt][2] * e0 + acc[mt][nt][3] * e1;
        }
#pragma unroll
    for (int off = 1; off < 4; off <<= 1)
#pragma unroll
        for (int r = 0; r < 4; r++) {
            s_part[r] += __shfl_xor_sync(0xffffffffu, s_part[r], off);
            d_part[r] += __shfl_xor_sync(0xffffffffu, d_part[r], off);
        }
    float* sS = (float*)smem;
    float* sD = sS + 128;
    __syncthreads();                       // smem (mma staging) free for reuse
    if ((wid & 1) == 0 && tg == 0) {
#pragma unroll
        for (int r = 0; r < 4; r++) {
            int lrow = wm + (r >> 1) * 16 + g + (r & 1) * 8;
            sS[lrow] = s_part[r];
            sD[lrow] = d_part[r];
        }
    }
    __syncthreads();
    if ((wid & 1) == 1 && tg == 0) {
#pragma unroll
        for (int r = 0; r < 4; r++) {
            int lrow = wm + (r >> 1) * 16 + g + (r & 1) * 8;
            int row = m0 + lrow;
            if (row < NN) {
                g_s[row * NH + head]  = sS[lrow] + s_part[r];
                g_dv[row * NH + head] = sD[lrow] + d_part[r];
            }
        }
    }
}

// ----------------------------- fused GAT (single pass) + stats ---------------
__global__ __launch_bounds__(256) void k_gat(const float* __restrict__ bias, int mode) {
    __shared__ float sv[8][256];
    int n = (blockIdx.x * blockDim.x + threadIdx.x) >> 5;
    int lane = threadIdx.x & 31;
    int wz = threadIdx.x >> 5;
    int p0 = __ldg(&g_segoff[n]);
    int p1 = __ldg(&g_segoff[n + 1]);
    float4 d4 = *(const float4*)(g_dv + n * NH);

    const bool hi = (lane >= 16);
    float4 den = make_float4(0.f, 0.f, 0.f, 0.f);
    float4 accA = make_float4(0.f, 0.f, 0.f, 0.f);
    float4 accB = make_float4(0.f, 0.f, 0.f, 0.f);
    for (int p = p0; p < p1; p++) {
        int s = __ldg(&g_ssrc[p]);
        float4 sval = *(const float4*)(g_s + s * NH);
        float e0 = __expf(lrelu(sval.x + d4.x, 0.2f));
        float e1 = __expf(lrelu(sval.y + d4.y, 0.2f));
        float e2 = __expf(lrelu(sval.z + d4.z, 0.2f));
        float e3 = __expf(lrelu(sval.w + d4.w, 0.2f));
        den.x += e0; den.y += e1; den.z += e2; den.w += e3;
        float w0 = hi ? e1 : e0;
        float w1 = hi ? e3 : e2;
        const float4* hp = (const float4*)(g_h + (size_t)s * HC);
        float4 v0 = __ldg(hp + lane);
        float4 v1 = __ldg(hp + lane + 32);
        accA.x = fmaf(w0, v0.x, accA.x); accA.y = fmaf(w0, v0.y, accA.y);
        accA.z = fmaf(w0, v0.z, accA.z); accA.w = fmaf(w0, v0.w, accA.w);
        accB.x = fmaf(w1, v1.x, accB.x); accB.y = fmaf(w1, v1.y, accB.y);
        accB.z = fmaf(w1, v1.z, accB.z); accB.w = fmaf(w1, v1.w, accB.w);
    }
    float inv0 = 1.f / (hi ? den.y : den.x);
    float inv1 = 1.f / (hi ? den.w : den.z);
    accA.x *= inv0; accA.y *= inv0; accA.z *= inv0; accA.w *= inv0;
    accB.x *= inv1; accB.y *= inv1; accB.z *= inv1; accB.w *= inv1;

    if (mode == 0) {
        float4* op = (float4*)(g_agg + (size_t)n * HC);
        op[lane] = accA;
        op[lane + 32] = accB;
        float4 bA = __ldg(((const float4*)bias) + lane);
        float4 bB = __ldg(((const float4*)bias) + lane + 32);
        *(float4*)&sv[wz][lane * 4] = make_float4(accA.x + bA.x, accA.y + bA.y,
                                                  accA.z + bA.z, accA.w + bA.w);
        *(float4*)&sv[wz][(lane + 32) * 4] = make_float4(accB.x + bB.x, accB.y + bB.y,
                                                         accB.z + bB.z, accB.w + bB.w);
        __syncthreads();
        int c = threadIdx.x;
        float s = 0.f, ss = 0.f;
#pragma unroll
        for (int w = 0; w < 8; w++) {
            float xv = sv[w][c];
            s += xv; ss += xv * xv;
        }
        red_add(&g_cs[c], s);
        red_add(&g_css[c], ss);
    } else {
        float4 tA, tB;
        tA.x = __shfl_xor_sync(0xffffffffu, accA.x, 16);
        tA.y = __shfl_xor_sync(0xffffffffu, accA.y, 16);
        tA.z = __shfl_xor_sync(0xffffffffu, accA.z, 16);
        tA.w = __shfl_xor_sync(0xffffffffu, accA.w, 16);
        tB.x = __shfl_xor_sync(0xffffffffu, accB.x, 16);
        tB.y = __shfl_xor_sync(0xffffffffu, accB.y, 16);
        tB.z = __shfl_xor_sync(0xffffffffu, accB.z, 16);
        tB.w = __shfl_xor_sync(0xffffffffu, accB.w, 16);
        if (!hi) {
            float4 m = make_float4(0.25f * (accA.x + tA.x + accB.x + tB.x),
                                   0.25f * (accA.y + tA.y + accB.y + tB.y),
                                   0.25f * (accA.z + tA.z + accB.z + tB.z),
                                   0.25f * (accA.w + tA.w + accB.w + tB.w));
            *(float4*)(g_act + (size_t)n * 64 + lane * 4) = m;
            float4 b4 = __ldg(((const float4*)bias) + lane);
            *(float4*)&sv[wz][lane * 4] = make_float4(m.x + b4.x, m.y + b4.y,
                                                      m.z + b4.z, m.w + b4.w);
        }
        __syncthreads();
        int c = threadIdx.x;
        if (c < 64) {
            float s = 0.f, ss = 0.f;
#pragma unroll
            for (int w = 0; w < 8; w++) {
                float xv = sv[w][c];
                s += xv; ss += xv * xv;
            }
            red_add(&g_cs[c], s);
            red_add(&g_css[c], ss);
        }
    }
}

// ----------------------------- scale (folds bias; self-zeroes stats) ---------
__global__ void k_scale(const float* __restrict__ ga, const float* __restrict__ gw,
                        const float* __restrict__ gb, const float* __restrict__ bias) {
    int c = threadIdx.x;
    float inv_n = 1.0f / (float)NN;
    float mu = g_cs[c] * inv_n;
    float ex2 = g_css[c] * inv_n;
    float a = ga[c];
    float var = ex2 - 2.f * a * mu * mu + a * a * mu * mu;
    float inv = rsqrtf(var + 1e-5f);
    float sc = gw[c] * inv;
    g_scale[c] = sc;
    g_shift[c] = gb[c] - sc * a * mu + sc * bias[c];
    g_cs[c] = 0.f;
    g_css[c] = 0.f;
}

// ----------------------------- fused norm + 3-layer MLP ----------------------
__global__ __launch_bounds__(256) void k_mlp(
    const float* __restrict__ mW0, const float* __restrict__ mb0,
    const float* __restrict__ mW1, const float* __restrict__ mb1,
    const float* __restrict__ mW2, const float* __restrict__ mb2,
    float* __restrict__ out) {
    __shared__ float W0s[64 * 32], W1s[32 * 16], W2s[16 * 2];
    __shared__ float b0s[32], b1s[16], b2s[2];
    int tid = threadIdx.x;
    for (int i = tid; i < 64 * 32; i += 256) W0s[i] = mW0[i];
    for (int i = tid; i < 32 * 16; i += 256) W1s[i] = mW1[i];
    if (tid < 32) W2s[tid] = mW2[tid];
    if (tid < 32) b0s[tid] = mb0[tid];
    if (tid < 16) b1s[tid] = mb1[tid];
    if (tid < 2)  b2s[tid] = mb2[tid];
    __syncthreads();

    int node = blockIdx.x * 256 + tid;
    if (node >= NN) return;

    float h1[32];
#pragma unroll
    for (int j = 0; j < 32; j++) h1[j] = b0s[j];
    const float* xr = g_act + (size_t)node * 64;
#pragma unroll 4
    for (int k = 0; k < 64; k++) {
        float v = lrelu(fmaf(xr[k], g_scale[k], g_shift[k]), 0.01f);
        const float4* wr = (const float4*)(W0s + k * 32);
#pragma unroll
        for (int j = 0; j < 8; j++) {
            float4 w = wr[j];
            h1[4 * j + 0] = fmaf(v, w.x, h1[4 * j + 0]);
            h1[4 * j + 1] = fmaf(v, w.y, h1[4 * j + 1]);
            h1[4 * j + 2] = fmaf(v, w.z, h1[4 * j + 2]);
            h1[4 * j + 3] = fmaf(v, w.w, h1[4 * j + 3]);
        }
    }
    float h2[16];
#pragma unroll
    for (int j = 0; j < 16; j++) h2[j] = b1s[j];
#pragma unroll
    for (int k = 0; k < 32; k++) {
        float v = fmaxf(h1[k], 0.f);
        const float4* wr = (const float4*)(W1s + k * 16);
#pragma unroll
        for (int j = 0; j < 4; j++) {
            float4 w = wr[j];
            h2[4 * j + 0] = fmaf(v, w.x, h2[4 * j + 0]);
            h2[4 * j + 1] = fmaf(v, w.y, h2[4 * j + 1]);
            h2[4 * j + 2] = fmaf(v, w.z, h2[4 * j + 2]);
            h2[4 * j + 3] = fmaf(v, w.w, h2[4 * j + 3]);
        }
    }
    float o0 = b2s[0], o1 = b2s[1];
#pragma unroll
    for (int k = 0; k < 16; k++) {
        float v = fmaxf(h2[k], 0.f);
        o0 = fmaf(v, W2s[k * 2], o0);
        o1 = fmaf(v, W2s[k * 2 + 1], o1);
    }
    *(float2*)(out + (size_t)node * 2) = make_float2(o0, o1);
}

// ----------------------------- driver ----------------------------------------
extern "C" void kernel_launch(void* const* d_in, const int* in_sizes, int n_in,
                              void* d_out, int out_size) {
    const float* x  = (const float*)d_in[0];
    const void*  ei = d_in[1];
    const float* W[3]   = { (const float*)d_in[2],  (const float*)d_in[9],  (const float*)d_in[16] };
    const float* as_[3] = { (const float*)d_in[3],  (const float*)d_in[10], (const float*)d_in[17] };
    const float* ad_[3] = { (const float*)d_in[4],  (const float*)d_in[11], (const float*)d_in[18] };
    const float* b_[3]  = { (const float*)d_in[5],  (const float*)d_in[12], (const float*)d_in[19] };
    const float* gw_[3] = { (const float*)d_in[6],  (const float*)d_in[13], (const float*)d_in[20] };
    const float* gb_[3] = { (const float*)d_in[7],  (const float*)d_in[14], (const float*)d_in[21] };
    const float* ga_[3] = { (const float*)d_in[8],  (const float*)d_in[15], (const float*)d_in[22] };
    const float* mW0 = (const float*)d_in[23]; const float* mb0 = (const float*)d_in[24];
    const float* mW1 = (const float*)d_in[25]; const float* mb1 = (const float*)d_in[26];
    const float* mW2 = (const float*)d_in[27]; const float* mb2 = (const float*)d_in[28];
    float* out = (float*)d_out;

    float* d_h;   cudaGetSymbolAddress((void**)&d_h,   g_h);
    float* d_agg; cudaGetSymbolAddress((void**)&d_agg, g_agg);
    __nv_bfloat16* d_WTh; cudaGetSymbolAddress((void**)&d_WTh, g_WTh);
    __nv_bfloat16* d_WTl; cudaGetSymbolAddress((void**)&d_WTl, g_WTl);

    // second stream for the edge-sort preamble (event fork/join; capturable)
    static cudaStream_t s2 = nullptr;
    static cudaEvent_t ev_fork = nullptr, ev_join = nullptr;
    if (!s2) {
        cudaStreamCreateWithFlags(&s2, cudaStreamNonBlocking);
        cudaEventCreateWithFlags(&ev_fork, cudaEventDisableTiming);
        cudaEventCreateWithFlags(&ev_join, cudaEventDisableTiming);
    }

    cudaEventRecord(ev_fork, 0);
    cudaStreamWaitEvent(s2, ev_fork, 0);
    k_zcnt<<<(NN + 255) / 256, 256, 0, s2>>>(ei);
    k_convhist<<<(2 * EE + 255) / 256, 256, 0, s2>>>(ei);
    k_scan1<<<NSCB, 256, 0, s2>>>();
    k_scan2<<<1, 256, 0, s2>>>();
    k_scan3<<<(NN + 255) / 256, 256, 0, s2>>>();
    k_scatter<<<(EPN + 255) / 256, 256, 0, s2>>>();
    cudaEventRecord(ev_join, s2);

    // main stream: weights + layer-0 GEMM overlap with the sort
    for (int L = 0; L < 3; L++) k_prep_w<<<256, 256>>>(W[L], L);

    const int GB = (NN + 127) / 128;
    for (int L = 0; L < 3; L++) {
        const float* Asrc = (L == 0) ? x : d_agg;
        if (L == 0)
            k_gemm<false><<<dim3(GB, 4), 256>>>(Asrc, d_WTh + (size_t)L * 65536,
                                                d_WTl + (size_t)L * 65536, as_[L], ad_[L], d_h);
        else
            k_gemm<true><<<dim3(GB, 4), 256>>>(Asrc, d_WTh + (size_t)L * 65536,
                                               d_WTl + (size_t)L * 65536, as_[L], ad_[L], d_h);
        if (L == 0) cudaStreamWaitEvent(0, ev_join, 0);   // sort must be done before gat
        int mode = (L == 2) ? 1 : 0;
        k_gat<<<(NN * 32 + 255) / 256, 256>>>(b_[L], mode);
        k_scale<<<1, (L == 2) ? 64 : 256>>>(ga_[L], gw_[L], gb_[L], b_[L]);
    }

    k_mlp<<<(NN + 255) / 256, 256>>>(mW0, mb0, mW1, mb1, mW2, mb2, out);
}